// round 1
// baseline (speedup 1.0000x reference)
#include <cuda_runtime.h>
#include <cuda_bf16.h>

// Problem constants (from reference):
//   img : (1, 64, 64, 1024) float32, NHWC
//   rois: (1, 512, 4) int32  -> (x, y, w, h)
//   out : (1, 512, 7, 7, 1024) float32
#define POOL   7
#define NROIS  512
#define IMG_H  64
#define IMG_W  64
#define IMG_C  1024

// One CTA per output cell (roi, py, px). 256 threads, each handles 4 channels
// via float4 (1024 channels = 256 * 4). Channels are innermost & contiguous
// in both img (NHWC) and out, so every load/store is a fully-coalesced 16B op.
__global__ __launch_bounds__(256, 8)
void roi_pool_kernel(const float* __restrict__ img,
                     const int*   __restrict__ rois,
                     float*       __restrict__ out)
{
    const int bid = blockIdx.x;            // roi*49 + py*7 + px
    const int roi = bid / (POOL * POOL);
    const int rem = bid - roi * (POOL * POOL);
    const int py  = rem / POOL;
    const int px  = rem - py * POOL;

    // ROI params (replicated per-thread; 16B aligned int4 load)
    const int4 r = __ldg(((const int4*)rois) + roi);
    const int x = r.x, y = r.y, w = r.z, h = r.w;

    // Match reference arithmetic: s = i * (dim/7.0f) in fp32
    const float sy = (float)py * ((float)h / (float)POOL);
    const float sx = (float)px * ((float)w / (float)POOL);
    const int y0 = (int)sy;                // sy >= 0, floor == trunc
    const int x0 = (int)sx;
    const float fy = sy - (float)y0;
    const float fx = sx - (float)x0;
    const int y1 = min(y0 + 1, h - 1);
    const int x1 = min(x0 + 1, w - 1);

    const int gy0 = y + y0, gy1 = y + y1;
    const int gx0 = x + x0, gx1 = x + x1;

    const float4* p00 = (const float4*)(img + ((size_t)(gy0 * IMG_W + gx0)) * IMG_C);
    const float4* p01 = (const float4*)(img + ((size_t)(gy0 * IMG_W + gx1)) * IMG_C);
    const float4* p10 = (const float4*)(img + ((size_t)(gy1 * IMG_W + gx0)) * IMG_C);
    const float4* p11 = (const float4*)(img + ((size_t)(gy1 * IMG_W + gx1)) * IMG_C);

    const int c = threadIdx.x;             // 0..255 -> float4 lane

    // Issue all four loads back-to-back for MLP before consuming.
    const float4 v00 = __ldg(p00 + c);
    const float4 v01 = __ldg(p01 + c);
    const float4 v10 = __ldg(p10 + c);
    const float4 v11 = __ldg(p11 + c);

    float4 o;
    {
        float t, b;
        t = v00.x + (v01.x - v00.x) * fx;
        b = v10.x + (v11.x - v10.x) * fx;
        o.x = t + (b - t) * fy;
        t = v00.y + (v01.y - v00.y) * fx;
        b = v10.y + (v11.y - v10.y) * fx;
        o.y = t + (b - t) * fy;
        t = v00.z + (v01.z - v00.z) * fx;
        b = v10.z + (v11.z - v10.z) * fx;
        o.z = t + (b - t) * fy;
        t = v00.w + (v01.w - v00.w) * fx;
        b = v10.w + (v11.w - v10.w) * fx;
        o.w = t + (b - t) * fy;
    }

    ((float4*)out)[(size_t)bid * 256 + c] = o;
}

extern "C" void kernel_launch(void* const* d_in, const int* in_sizes, int n_in,
                              void* d_out, int out_size)
{
    const float* img  = (const float*)d_in[0];
    const int*   rois = (const int*)d_in[1];
    float*       out  = (float*)d_out;

    const int grid = NROIS * POOL * POOL;   // 25088
    roi_pool_kernel<<<grid, 256>>>(img, rois, out);
}

// round 2
// speedup vs baseline: 1.0763x; 1.0763x over previous
#include <cuda_runtime.h>
#include <cuda_bf16.h>

// img : (1, 64, 64, 1024) float32, NHWC
// rois: (1, 512, 4) int32  -> (x, y, w, h)
// out : (1, 512, 7, 7, 1024) float32
#define POOL   7
#define NROIS  512
#define IMG_W  64
#define IMG_C  1024

// One CTA per output cell (roi, py, px). 128 threads; each thread produces
// TWO float4s (channels c and c+128 of 256 float4 lanes) -> 8 independent
// 16B loads in flight per thread, index math amortized over 2x the data.
__global__ __launch_bounds__(128)
void roi_pool_kernel(const float* __restrict__ img,
                     const int*   __restrict__ rois,
                     float*       __restrict__ out)
{
    const int bid = blockIdx.x;            // roi*49 + py*7 + px
    const int roi = bid / (POOL * POOL);
    const int rem = bid - roi * (POOL * POOL);
    const int py  = rem / POOL;
    const int px  = rem - py * POOL;

    const int4 r = __ldg(((const int4*)rois) + roi);
    const int x = r.x, y = r.y, w = r.z, h = r.w;

    // Match reference arithmetic: s = i * (dim/7.0f) in fp32
    const float sy = (float)py * ((float)h / (float)POOL);
    const float sx = (float)px * ((float)w / (float)POOL);
    const int y0 = (int)sy;
    const int x0 = (int)sx;
    const float fy = sy - (float)y0;
    const float fx = sx - (float)x0;
    const int y1 = min(y0 + 1, h - 1);
    const int x1 = min(x0 + 1, w - 1);

    // Bilinear weights (weighted-sum form: 1 MUL + 3 FMA per scalar)
    const float w11 = fx * fy;
    const float w01 = fx - w11;            // fx*(1-fy)
    const float w10 = fy - w11;            // (1-fx)*fy
    const float w00 = 1.0f - fx - w10;     // (1-fx)*(1-fy)

    const int gy0 = y + y0, gy1 = y + y1;
    const int gx0 = x + x0, gx1 = x + x1;

    const float4* p00 = (const float4*)(img + ((size_t)(gy0 * IMG_W + gx0)) * IMG_C);
    const float4* p01 = (const float4*)(img + ((size_t)(gy0 * IMG_W + gx1)) * IMG_C);
    const float4* p10 = (const float4*)(img + ((size_t)(gy1 * IMG_W + gx0)) * IMG_C);
    const float4* p11 = (const float4*)(img + ((size_t)(gy1 * IMG_W + gx1)) * IMG_C);

    const int c0 = threadIdx.x;            // 0..127
    const int c1 = c0 + 128;               // 128..255

    // 8 independent 16B loads, issued back-to-back for max MLP.
    const float4 a00 = __ldg(p00 + c0);
    const float4 a01 = __ldg(p01 + c0);
    const float4 a10 = __ldg(p10 + c0);
    const float4 a11 = __ldg(p11 + c0);
    const float4 b00 = __ldg(p00 + c1);
    const float4 b01 = __ldg(p01 + c1);
    const float4 b10 = __ldg(p10 + c1);
    const float4 b11 = __ldg(p11 + c1);

    float4 oa, ob;
    oa.x = fmaf(a11.x, w11, fmaf(a10.x, w10, fmaf(a01.x, w01, a00.x * w00)));
    oa.y = fmaf(a11.y, w11, fmaf(a10.y, w10, fmaf(a01.y, w01, a00.y * w00)));
    oa.z = fmaf(a11.z, w11, fmaf(a10.z, w10, fmaf(a01.z, w01, a00.z * w00)));
    oa.w = fmaf(a11.w, w11, fmaf(a10.w, w10, fmaf(a01.w, w01, a00.w * w00)));
    ob.x = fmaf(b11.x, w11, fmaf(b10.x, w10, fmaf(b01.x, w01, b00.x * w00)));
    ob.y = fmaf(b11.y, w11, fmaf(b10.y, w10, fmaf(b01.y, w01, b00.y * w00)));
    ob.z = fmaf(b11.z, w11, fmaf(b10.z, w10, fmaf(b01.z, w01, b00.z * w00)));
    ob.w = fmaf(b11.w, w11, fmaf(b10.w, w10, fmaf(b01.w, w01, b00.w * w00)));

    float4* o = (float4*)out + (size_t)bid * 256;
    o[c0] = oa;
    o[c1] = ob;
}

extern "C" void kernel_launch(void* const* d_in, const int* in_sizes, int n_in,
                              void* d_out, int out_size)
{
    const float* img  = (const float*)d_in[0];
    const int*   rois = (const int*)d_in[1];
    float*       out  = (float*)d_out;

    const int grid = NROIS * POOL * POOL;   // 25088
    roi_pool_kernel<<<grid, 128>>>(img, rois, out);
}